// round 6
// baseline (speedup 1.0000x reference)
#include <cuda_runtime.h>

// Social_Aggregator: per-(node,neighbor) 4-layer MLP + ragged masked softmax
// aggregate. Persistent blocks (1/SM), warp-level dynamic work stealing over
// nodes, NB=8 neighbors in flight, software-pipelined gather (prefetch next
// batch's embeddings/labels into registers during compute), online softmax.
// Weights staged once per block in smem; compute via packed fma.rn.f32x2.

#define BNODES   16384
#define KMAX     50
#define DD       64
#define RR       8
#define NWARP    16
#define NTHREADS (NWARP * 32)
#define NB       8
#define GRID     152            // GB300: 152 SMs

#define W1_PAIRS 36   // (DD+RR)/2
#define M_PAIRS  32   // DD/2

// shared memory layout (bytes)
#define SZ_W1    (W1_PAIRS * 32 * 16)   // 18432
#define SZ_M     (M_PAIRS  * 32 * 16)   // 16384
#define OFF_W1   0
#define OFF_W2   (OFF_W1  + SZ_W1)
#define OFF_A1O  (OFF_W2  + SZ_M)
#define OFF_A1U  (OFF_A1O + SZ_M)
#define OFF_A2   (OFF_A1U + SZ_M)
#define OFF_A3   (OFF_A2  + SZ_M)       // 64 floats
#define OFF_B1   (OFF_A3  + 256)
#define OFF_B2   (OFF_B1  + 256)
#define OFF_BA1  (OFF_B2  + 256)
#define OFF_BA2  (OFF_BA1 + 256)
#define OFF_WBUF (OFF_BA2 + 256)        // 85248
#define SLOT_BYTES 576                  // 36 ulonglong2 per neighbor slot (dup format)
#define WARPBUF    (NB * SLOT_BYTES)    // 4608 (u_rep dup aliases slot 0)
#define SMEM_TOTAL (OFF_WBUF + NWARP * WARPBUF)   // 158976 -> 1 block, 16 warps/SM

typedef unsigned long long u64;

__device__ unsigned int g_ctr;

__global__ void reset_ctr() { g_ctr = 0u; }

static __device__ __forceinline__ u64 pk(float lo, float hi) {
    u64 r; asm("mov.b64 %0, {%1, %2};" : "=l"(r) : "f"(lo), "f"(hi)); return r;
}
static __device__ __forceinline__ void upk(u64 v, float& lo, float& hi) {
    asm("mov.b64 {%0, %1}, %2;" : "=f"(lo), "=f"(hi) : "l"(v));
}
static __device__ __forceinline__ u64 ffma2(u64 a, u64 b, u64 c) {
    u64 r; asm("fma.rn.f32x2 %0, %1, %2, %3;" : "=l"(r) : "l"(a), "l"(b), "l"(c)); return r;
}
static __device__ __forceinline__ u64 fmul2(u64 a, u64 b) {
    u64 r; asm("mul.rn.f32x2 %0, %1, %2;" : "=l"(r) : "l"(a), "l"(b)); return r;
}

// NB-neighbor fused layer: 64-wide output, lane owns cols (2*lane, 2*lane+1).
// W packed: entry (p, lane) = {W[2p][2l], W[2p][2l+1], W[2p+1][2l], W[2p+1][2l+1]}
// x buffers: entry p = {dup(x[2p]), dup(x[2p+1])}  (broadcast LDS.128)
template<int PAIRS>
static __device__ __forceinline__ void mlpN(
    const ulonglong2* __restrict__ W,
    ulonglong2* const* __restrict__ xb,
    int lane, u64* __restrict__ c)
{
#pragma unroll 2
    for (int p = 0; p < PAIRS; p++) {
        ulonglong2 w = W[p * 32 + lane];
#pragma unroll
        for (int j = 0; j < NB; j++) {
            ulonglong2 x = xb[j][p];
            c[j] = ffma2(x.x, w.x, c[j]);
            c[j] = ffma2(x.y, w.y, c[j]);
        }
    }
}

// relu accumulator, store duplicated pair to buf[lane], return packed relu'd val
static __device__ __forceinline__ u64 relu_dup(u64 acc, ulonglong2* buf, int lane) {
    float v0, v1; upk(acc, v0, v1);
    v0 = fmaxf(v0, 0.f); v1 = fmaxf(v1, 0.f);
    ulonglong2 t; t.x = pk(v0, v0); t.y = pk(v1, v1);
    buf[lane] = t;
    return pk(v0, v1);
}

static __device__ __forceinline__ float wsum(float v) {
#pragma unroll
    for (int o = 16; o; o >>= 1) v += __shfl_xor_sync(0xffffffffu, v, o);
    return v;
}

static __device__ __forceinline__ void smax_upd(float s, u64 o, float& m, float& l, u64& agg) {
    float mn   = fmaxf(m, s);
    float corr = __expf(m - mn);
    float pw   = __expf(s - mn);
    l   = l * corr + pw;
    agg = ffma2(agg, pk(corr, corr), fmul2(o, pk(pw, pw)));
    m   = mn;
}

static __device__ __forceinline__ void pack_mat(
    const float* __restrict__ g, float4* __restrict__ dst,
    int pairs, int rowoff, int tid)
{
    for (int idx = tid; idx < pairs * 32; idx += NTHREADS) {
        int p = idx >> 5, l = idx & 31;
        const float* r0 = g + (rowoff + 2 * p) * DD + 2 * l;
        dst[idx] = make_float4(r0[0], r0[1], r0[DD], r0[DD + 1]);
    }
}

// prefetch batch starting at k0 into registers (no smem traffic)
static __device__ __forceinline__ void gather_ld(
    int k0, int base, int lane, int ls, int lc,
    const int* __restrict__ nidx, const float* __restrict__ u2e,
    const float* __restrict__ labels,
    float2* __restrict__ pe, float2& plb)
{
    int myk = k0 + lane; if (myk > KMAX - 1) myk = KMAX - 1;  // clamp: garbage slot ok
    int idxv = (lane < NB) ? nidx[base + myk] : 0;
#pragma unroll
    for (int j = 0; j < NB; j++) {
        int n = __shfl_sync(0xffffffffu, idxv, j);
        pe[j] = *(const float2*)(u2e + (size_t)n * DD + 2 * lane);
    }
    int kk = k0 + ls; if (kk > KMAX - 1) kk = KMAX - 1;
    plb = *(const float2*)(labels + (size_t)(base + kk) * RR + 2 * lc);
}

// commit prefetched registers to the dup-format smem slots
static __device__ __forceinline__ void gather_st(
    ulonglong2* const* __restrict__ xb, int lane, int ls, int lc,
    const float2* __restrict__ pe, float2 plb)
{
#pragma unroll
    for (int j = 0; j < NB; j++) {
        ulonglong2 t; t.x = pk(pe[j].x, pe[j].x); t.y = pk(pe[j].y, pe[j].y);
        xb[j][lane] = t;
    }
    ulonglong2 tl; tl.x = pk(plb.x, plb.x); tl.y = pk(plb.y, plb.y);
    xb[ls][32 + lc] = tl;   // 32 lanes cover 8 slots x 4 label pairs exactly
}

__global__ __launch_bounds__(NTHREADS, 1)
void sagg_kernel(
    const int*   __restrict__ nodes,
    const int*   __restrict__ nidx,
    const int*   __restrict__ nlen,
    const float* __restrict__ labels,
    const float* __restrict__ u2e,
    const float* __restrict__ w1W, const float* __restrict__ w1b,
    const float* __restrict__ w2W, const float* __restrict__ w2b,
    const float* __restrict__ a1W, const float* __restrict__ a1b,
    const float* __restrict__ a2W, const float* __restrict__ a2b,
    const float* __restrict__ a3W, const float* __restrict__ a3b,
    float* __restrict__ out)
{
    extern __shared__ char sm[];
    const int tid = threadIdx.x;

    // ---- stage packed weights into smem (once per block) ----
    pack_mat(w1W, (float4*)(sm + OFF_W1),  W1_PAIRS, 0,  tid);
    pack_mat(w2W, (float4*)(sm + OFF_W2),  M_PAIRS,  0,  tid);
    pack_mat(a1W, (float4*)(sm + OFF_A1O), M_PAIRS,  0,  tid);   // rows 0..63   (o part)
    pack_mat(a1W, (float4*)(sm + OFF_A1U), M_PAIRS,  64, tid);   // rows 64..127 (u part)
    pack_mat(a2W, (float4*)(sm + OFF_A2),  M_PAIRS,  0,  tid);
    if (tid < 64) {
        ((float*)(sm + OFF_A3 ))[tid] = a3W[tid];
        ((float*)(sm + OFF_B1 ))[tid] = w1b[tid];
        ((float*)(sm + OFF_B2 ))[tid] = w2b[tid];
        ((float*)(sm + OFF_BA1))[tid] = a1b[tid];
        ((float*)(sm + OFF_BA2))[tid] = a2b[tid];
    }
    __syncthreads();

    const int warp = tid >> 5, lane = tid & 31;
    const int ls = lane >> 2, lc = lane & 3;   // label slot / pair owned by this lane

    const ulonglong2* W1  = (const ulonglong2*)(sm + OFF_W1);
    const ulonglong2* W2  = (const ulonglong2*)(sm + OFF_W2);
    const ulonglong2* A1O = (const ulonglong2*)(sm + OFF_A1O);
    const ulonglong2* A1U = (const ulonglong2*)(sm + OFF_A1U);
    const ulonglong2* A2  = (const ulonglong2*)(sm + OFF_A2);
    const float* A3s = (const float*)(sm + OFF_A3);
    const float* B1s = (const float*)(sm + OFF_B1);
    const float* B2s = (const float*)(sm + OFF_B2);
    const float* BA1 = (const float*)(sm + OFF_BA1);
    const float* BA2 = (const float*)(sm + OFF_BA2);

    char* wb = sm + OFF_WBUF + warp * WARPBUF;
    ulonglong2* xb[NB];
#pragma unroll
    for (int j = 0; j < NB; j++) xb[j] = (ulonglong2*)(wb + j * SLOT_BYTES);

    // loop-invariant packed biases
    const u64 bb1  = pk(B1s[2 * lane], B1s[2 * lane + 1]);
    const u64 bb2  = pk(B2s[2 * lane], B2s[2 * lane + 1]);
    const u64 bba2 = pk(BA2[2 * lane], BA2[2 * lane + 1]);
    const float a3lo = A3s[2 * lane], a3hi = A3s[2 * lane + 1];
    const float a3bias = a3b[0];

    // ---- persistent loop: warp-level dynamic node stealing ----
    for (;;) {
        int b = 0;
        if (lane == 0) b = (int)atomicAdd(&g_ctr, 1u);
        b = __shfl_sync(0xffffffffu, b, 0);
        if (b >= BNODES) break;

        const int len  = nlen[b];
        const int node = nodes[b];
        const float2 ur = *(const float2*)(u2e + (size_t)node * DD + 2 * lane);

        if (len == 0) {   // zero-neighbor fallback: own embedding
            *(float2*)(out + (size_t)b * DD + 2 * lane) = ur;
            continue;
        }

        // u_rep dup (aliases slot 0, restaged later) + per-node precompute:
        // uc = u_rep @ a1_W[64:] + a1_b
        {
            ulonglong2 t; t.x = pk(ur.x, ur.x); t.y = pk(ur.y, ur.y);
            xb[0][lane] = t;
        }
        __syncwarp();

        u64 uc = pk(BA1[2 * lane], BA1[2 * lane + 1]);
#pragma unroll 4
        for (int p = 0; p < M_PAIRS; p++) {
            ulonglong2 w = A1U[p * 32 + lane];
            ulonglong2 x = xb[0][p];
            uc = ffma2(x.x, w.x, uc);
            uc = ffma2(x.y, w.y, uc);
        }
        __syncwarp();

        float mrun = -3.0e38f, lrun = 0.f;
        u64 agg = 0ULL;
        const int base = b * KMAX;

        // software-pipelined gather: prefetch batch 0 now
        float2 pe[NB]; float2 plb;
        gather_ld(0, base, lane, ls, lc, nidx, u2e, labels, pe, plb);

        for (int k0 = 0; k0 < len; k0 += NB) {
            int nv = len - k0; if (nv > NB) nv = NB;

            // commit prefetched batch to smem slots
            gather_st(xb, lane, ls, lc, pe, plb);
            __syncwarp();

            // issue next batch's gather; latency overlaps the 4 MLP layers
            if (k0 + NB < len)
                gather_ld(k0 + NB, base, lane, ls, lc, nidx, u2e, labels, pe, plb);

            // ---- layer 1: x(72) -> h(64), relu ----
            u64 c[NB];
#pragma unroll
            for (int j = 0; j < NB; j++) c[j] = bb1;
            mlpN<W1_PAIRS>(W1, xb, lane, c);
            __syncwarp();
#pragma unroll
            for (int j = 0; j < NB; j++) relu_dup(c[j], xb[j], lane);
            __syncwarp();

            // ---- layer 2: h(64) -> o(64), relu; o kept in registers ----
#pragma unroll
            for (int j = 0; j < NB; j++) c[j] = bb2;
            mlpN<M_PAIRS>(W2, xb, lane, c);
            __syncwarp();
            u64 o[NB];
#pragma unroll
            for (int j = 0; j < NB; j++) o[j] = relu_dup(c[j], xb[j], lane);
            __syncwarp();

            // ---- attention layer 1: o@a1[:64] + (u_rep@a1[64:] + b) ----
#pragma unroll
            for (int j = 0; j < NB; j++) c[j] = uc;
            mlpN<M_PAIRS>(A1O, xb, lane, c);
            __syncwarp();
#pragma unroll
            for (int j = 0; j < NB; j++) relu_dup(c[j], xb[j], lane);
            __syncwarp();

            // ---- attention layer 2: 64 -> 64, relu (stays in registers) ----
#pragma unroll
            for (int j = 0; j < NB; j++) c[j] = bba2;
            mlpN<M_PAIRS>(A2, xb, lane, c);

            // ---- scores + online softmax accumulate (valid slots only) ----
#pragma unroll
            for (int j = 0; j < NB; j++) {
                float v0, v1; upk(c[j], v0, v1);
                v0 = fmaxf(v0, 0.f); v1 = fmaxf(v1, 0.f);
                float s = wsum(v0 * a3lo + v1 * a3hi) + a3bias;
                if (nv > j) smax_upd(s, o[j], mrun, lrun, agg);
            }
        }

        float inv = 1.0f / lrun;
        float g0, g1; upk(agg, g0, g1);
        *(float2*)(out + (size_t)b * DD + 2 * lane) = make_float2(g0 * inv, g1 * inv);
    }
}

extern "C" void kernel_launch(void* const* d_in, const int* in_sizes, int n_in,
                              void* d_out, int out_size)
{
    (void)in_sizes; (void)n_in; (void)out_size;
    cudaFuncSetAttribute(sagg_kernel, cudaFuncAttributeMaxDynamicSharedMemorySize, SMEM_TOTAL);

    const int*   nodes  = (const int*)  d_in[0];
    const int*   nidx   = (const int*)  d_in[1];
    const int*   nlen   = (const int*)  d_in[2];
    const float* labels = (const float*)d_in[3];
    const float* u2e    = (const float*)d_in[4];
    const float* w1W    = (const float*)d_in[5];
    const float* w1b    = (const float*)d_in[6];
    const float* w2W    = (const float*)d_in[7];
    const float* w2b    = (const float*)d_in[8];
    const float* a1W    = (const float*)d_in[9];
    const float* a1b    = (const float*)d_in[10];
    const float* a2W    = (const float*)d_in[11];
    const float* a2b    = (const float*)d_in[12];
    const float* a3W    = (const float*)d_in[13];
    const float* a3b    = (const float*)d_in[14];

    reset_ctr<<<1, 1>>>();
    sagg_kernel<<<GRID, NTHREADS, SMEM_TOTAL>>>(
        nodes, nidx, nlen, labels, u2e,
        w1W, w1b, w2W, w2b, a1W, a1b, a2W, a2b, a3W, a3b,
        (float*)d_out);
}

// round 11
// speedup vs baseline: 1.5437x; 1.5437x over previous
#include <cuda_runtime.h>

// Social_Aggregator: persistent blocks + warp work stealing, NB=8 neighbors,
// online softmax. Activations stored as NEIGHBOR-PAIRS ({x_j0[i], x_j1[i]}
// per 8B entry): one broadcast LDS.128 feeds 4 FFMA2, no dup movs on x side;
// W dup'd in registers (ALU headroom). Ping-pong A/B activation buffers cut
// warp syncs to 4/batch. Lane owns output cols l and l+32. fp32-exact.

#define BNODES   16384
#define KMAX     50
#define DD       64
#define RR       8
#define NWARP    16
#define NTHREADS (NWARP * 32)
#define NB       8
#define NPAIR    (NB / 2)
#define GRID     152

#define W1_IP    36   // (DD+RR)/2 input-pairs
#define M_IP     32   // DD/2

// shared memory layout (bytes)
#define SZ_W1    (W1_IP * 32 * 16)   // 18432
#define SZ_M     (M_IP  * 32 * 16)   // 16384
#define OFF_W1   0
#define OFF_W2   (OFF_W1  + SZ_W1)
#define OFF_A1O  (OFF_W2  + SZ_M)
#define OFF_A1U  (OFF_A1O + SZ_M)
#define OFF_A2   (OFF_A1U + SZ_M)
#define OFF_A3   (OFF_A2  + SZ_M)       // 64 floats
#define OFF_B1   (OFF_A3  + 256)
#define OFF_B2   (OFF_B1  + 256)
#define OFF_BA1  (OFF_B2  + 256)
#define OFF_BA2  (OFF_BA1 + 256)
#define OFF_WBUF (OFF_BA2 + 256)        // 85248
#define SLOTA_BYTES 576                 // 72 u64: x pairs (64) + label pairs (8)
#define SLOTB_BYTES 512                 // 64 u64: hidden pairs
#define WARPBUF    (NPAIR * (SLOTA_BYTES + SLOTB_BYTES))   // 4352
#define SMEM_TOTAL (OFF_WBUF + NWARP * WARPBUF)            // 154880

typedef unsigned long long u64;

__device__ unsigned int g_ctr;
__global__ void reset_ctr() { g_ctr = 0u; }

static __device__ __forceinline__ u64 pk(float lo, float hi) {
    u64 r; asm("mov.b64 %0, {%1, %2};" : "=l"(r) : "f"(lo), "f"(hi)); return r;
}
static __device__ __forceinline__ void upk(u64 v, float& lo, float& hi) {
    asm("mov.b64 {%0, %1}, %2;" : "=f"(lo), "=f"(hi) : "l"(v));
}
static __device__ __forceinline__ u64 ffma2(u64 a, u64 b, u64 c) {
    u64 r; asm("fma.rn.f32x2 %0, %1, %2, %3;" : "=l"(r) : "l"(a), "l"(b), "l"(c)); return r;
}
static __device__ __forceinline__ u64 fmul2(u64 a, u64 b) {
    u64 r; asm("mul.rn.f32x2 %0, %1, %2;" : "=l"(r) : "l"(a), "l"(b)); return r;
}
static __device__ __forceinline__ u64 add2(u64 a, u64 b) {
    u64 r; asm("add.rn.f32x2 %0, %1, %2;" : "=l"(r) : "l"(a), "l"(b)); return r;
}
static __device__ __forceinline__ u64 relu2(u64 v) {
    float a, b; upk(v, a, b);
    return pk(fmaxf(a, 0.f), fmaxf(b, 0.f));
}
// packed warp sum: reduces both f32 halves simultaneously
static __device__ __forceinline__ u64 wsum2(u64 v) {
#pragma unroll
    for (int o = 16; o; o >>= 1)
        v = add2(v, __shfl_xor_sync(0xffffffffu, v, o));
    return v;
}
static __device__ __forceinline__ void smax_upd(float s, u64 o, float& m, float& l, u64& agg) {
    float mn   = fmaxf(m, s);
    float corr = __expf(m - mn);
    float pw   = __expf(s - mn);
    l   = l * corr + pw;
    agg = ffma2(agg, pk(corr, corr), fmul2(o, pk(pw, pw)));
    m   = mn;
}

// W pack: entry (ip, lane) = {W[2ip][l], W[2ip][l+32], W[2ip+1][l], W[2ip+1][l+32]}
static __device__ __forceinline__ void pack_mat(
    const float* __restrict__ g, float4* __restrict__ dst,
    int ipairs, int rowoff, int tid)
{
    for (int idx = tid; idx < ipairs * 32; idx += NTHREADS) {
        int ip = idx >> 5, l = idx & 31;
        const float* r0 = g + (rowoff + 2 * ip) * DD;
        const float* r1 = r0 + DD;
        dst[idx] = make_float4(r0[l], r0[l + 32], r1[l], r1[l + 32]);
    }
}

// fused layer over NPAIR neighbor-pair slots.
// per ip: 1 spread LDS.128 (W) + NPAIR broadcast LDS.128 (x) -> 4*NPAIR FFMA2.
// c layout: c[jj*2+0] = {out_j0[l], out_j1[l]}, c[jj*2+1] = {out_j0[l+32], out_j1[l+32]}
template<int IPAIRS>
static __device__ __forceinline__ void mlpP(
    const ulonglong2* __restrict__ W,
    const ulonglong2* const* __restrict__ xb,
    int lane, u64* __restrict__ c)
{
#pragma unroll 2
    for (int ip = 0; ip < IPAIRS; ip++) {
        ulonglong2 w4 = W[ip * 32 + lane];
        float wA, wB, wC, wD;
        upk(w4.x, wA, wB);   // W[2ip][l], W[2ip][l+32]
        upk(w4.y, wC, wD);   // W[2ip+1][l], W[2ip+1][l+32]
        u64 wA2 = pk(wA, wA), wB2 = pk(wB, wB);
        u64 wC2 = pk(wC, wC), wD2 = pk(wD, wD);
#pragma unroll
        for (int jj = 0; jj < NPAIR; jj++) {
            ulonglong2 xp = xb[jj][ip];
            c[jj * 2 + 0] = ffma2(xp.x, wA2, c[jj * 2 + 0]);
            c[jj * 2 + 0] = ffma2(xp.y, wC2, c[jj * 2 + 0]);
            c[jj * 2 + 1] = ffma2(xp.x, wB2, c[jj * 2 + 1]);
            c[jj * 2 + 1] = ffma2(xp.y, wD2, c[jj * 2 + 1]);
        }
    }
}

__global__ __launch_bounds__(NTHREADS, 1)
void sagg_kernel(
    const int*   __restrict__ nodes,
    const int*   __restrict__ nidx,
    const int*   __restrict__ nlen,
    const float* __restrict__ labels,
    const float* __restrict__ u2e,
    const float* __restrict__ w1W, const float* __restrict__ w1b,
    const float* __restrict__ w2W, const float* __restrict__ w2b,
    const float* __restrict__ a1W, const float* __restrict__ a1b,
    const float* __restrict__ a2W, const float* __restrict__ a2b,
    const float* __restrict__ a3W, const float* __restrict__ a3b,
    float* __restrict__ out)
{
    extern __shared__ char sm[];
    const int tid = threadIdx.x;

    pack_mat(w1W, (float4*)(sm + OFF_W1),  W1_IP, 0,  tid);
    pack_mat(w2W, (float4*)(sm + OFF_W2),  M_IP,  0,  tid);
    pack_mat(a1W, (float4*)(sm + OFF_A1O), M_IP,  0,  tid);   // a1 rows 0..63 (o)
    pack_mat(a1W, (float4*)(sm + OFF_A1U), M_IP,  64, tid);   // a1 rows 64..127 (u)
    pack_mat(a2W, (float4*)(sm + OFF_A2),  M_IP,  0,  tid);
    if (tid < 64) {
        ((float*)(sm + OFF_A3 ))[tid] = a3W[tid];
        ((float*)(sm + OFF_B1 ))[tid] = w1b[tid];
        ((float*)(sm + OFF_B2 ))[tid] = w2b[tid];
        ((float*)(sm + OFF_BA1))[tid] = a1b[tid];
        ((float*)(sm + OFF_BA2))[tid] = a2b[tid];
    }
    __syncthreads();

    const int warp = tid >> 5, lane = tid & 31;
    const int ljj = lane >> 3, lr = lane & 7;   // label staging: pair slot / r owned

    const ulonglong2* W1  = (const ulonglong2*)(sm + OFF_W1);
    const ulonglong2* W2  = (const ulonglong2*)(sm + OFF_W2);
    const ulonglong2* A1O = (const ulonglong2*)(sm + OFF_A1O);
    const ulonglong2* A1U = (const ulonglong2*)(sm + OFF_A1U);
    const ulonglong2* A2  = (const ulonglong2*)(sm + OFF_A2);
    const float* A3s = (const float*)(sm + OFF_A3);
    const float* B1s = (const float*)(sm + OFF_B1);
    const float* B2s = (const float*)(sm + OFF_B2);
    const float* BA1 = (const float*)(sm + OFF_BA1);
    const float* BA2 = (const float*)(sm + OFF_BA2);

    char* wb = sm + OFF_WBUF + warp * WARPBUF;
    u64*              xsA[NPAIR];  u64*              xsB[NPAIR];
    const ulonglong2* xbA[NPAIR];  const ulonglong2* xbB[NPAIR];
#pragma unroll
    for (int jj = 0; jj < NPAIR; jj++) {
        xsA[jj] = (u64*)(wb + jj * SLOTA_BYTES);
        xsB[jj] = (u64*)(wb + NPAIR * SLOTA_BYTES + jj * SLOTB_BYTES);
        xbA[jj] = (const ulonglong2*)xsA[jj];
        xbB[jj] = (const ulonglong2*)xsB[jj];
    }

    // loop-invariant packed biases (dup form: same scalar both halves)
    const u64 bb1_0  = pk(B1s[lane],      B1s[lane]);
    const u64 bb1_1  = pk(B1s[lane + 32], B1s[lane + 32]);
    const u64 bb2_0  = pk(B2s[lane],      B2s[lane]);
    const u64 bb2_1  = pk(B2s[lane + 32], B2s[lane + 32]);
    const u64 bba2_0 = pk(BA2[lane],      BA2[lane]);
    const u64 bba2_1 = pk(BA2[lane + 32], BA2[lane + 32]);
    const u64 a3d0   = pk(A3s[lane],      A3s[lane]);
    const u64 a3d1   = pk(A3s[lane + 32], A3s[lane + 32]);
    const float a3bias = a3b[0];

    // ---- persistent loop: warp-level dynamic node stealing ----
    for (;;) {
        int b = 0;
        if (lane == 0) b = (int)atomicAdd(&g_ctr, 1u);
        b = __shfl_sync(0xffffffffu, b, 0);
        if (b >= BNODES) break;

        const int len  = nlen[b];
        const int node = nodes[b];
        const float2 ur = *(const float2*)(u2e + (size_t)node * DD + 2 * lane);

        if (len == 0) {   // zero-neighbor fallback: own embedding
            *(float2*)(out + (size_t)b * DD + 2 * lane) = ur;
            continue;
        }

        // self-pair staging into slot A0 for the uc precompute
        ((float4*)xsA[0])[lane] = make_float4(ur.x, ur.x, ur.y, ur.y);
        __syncwarp();

        // uc = u_rep @ a1_W[64:] + a1_b, directly in dup form
        u64 ucd0 = pk(BA1[lane],      BA1[lane]);
        u64 ucd1 = pk(BA1[lane + 32], BA1[lane + 32]);
#pragma unroll 2
        for (int ip = 0; ip < M_IP; ip++) {
            ulonglong2 w4 = A1U[ip * 32 + lane];
            float wA, wB, wC, wD;
            upk(w4.x, wA, wB); upk(w4.y, wC, wD);
            ulonglong2 xp = xbA[0][ip];
            ucd0 = ffma2(xp.x, pk(wA, wA), ucd0);
            ucd0 = ffma2(xp.y, pk(wC, wC), ucd0);
            ucd1 = ffma2(xp.x, pk(wB, wB), ucd1);
            ucd1 = ffma2(xp.y, pk(wD, wD), ucd1);
        }
        __syncwarp();   // orders uc reads of A0 before first staging write

        float mrun = -3.0e38f, lrun = 0.f;
        u64 agg = 0ULL;                 // {agg[l], agg[l+32]}
        const int base = b * KMAX;

        // ---- software-pipelined gather: prefetch batch 0 ----
        float2 pe[NB]; float plb0, plb1;
        {
            int myk = min(0 + lane, KMAX - 1);
            int idxv = (lane < NB) ? nidx[base + myk] : 0;
#pragma unroll
            for (int j = 0; j < NB; j++) {
                int n = __shfl_sync(0xffffffffu, idxv, j);
                pe[j] = *(const float2*)(u2e + (size_t)n * DD + 2 * lane);
            }
            int kk0 = min(2 * ljj,     KMAX - 1);
            int kk1 = min(2 * ljj + 1, KMAX - 1);
            plb0 = labels[(size_t)(base + kk0) * RR + lr];
            plb1 = labels[(size_t)(base + kk1) * RR + lr];
        }

        for (int k0 = 0; k0 < len; k0 += NB) {
            int nv = len - k0; if (nv > NB) nv = NB;

            // commit prefetched batch into A slots (x pairs + label pairs)
#pragma unroll
            for (int jj = 0; jj < NPAIR; jj++)
                ((float4*)xsA[jj])[lane] = make_float4(
                    pe[2 * jj].x, pe[2 * jj + 1].x, pe[2 * jj].y, pe[2 * jj + 1].y);
            xsA[ljj][DD + lr] = pk(plb0, plb1);
            __syncwarp();   // sync 1: staging RAW

            // prefetch next batch during compute
            if (k0 + NB < len) {
                int k1 = k0 + NB;
                int myk = min(k1 + lane, KMAX - 1);
                int idxv = (lane < NB) ? nidx[base + myk] : 0;
#pragma unroll
                for (int j = 0; j < NB; j++) {
                    int n = __shfl_sync(0xffffffffu, idxv, j);
                    pe[j] = *(const float2*)(u2e + (size_t)n * DD + 2 * lane);
                }
                int kk0 = min(k1 + 2 * ljj,     KMAX - 1);
                int kk1 = min(k1 + 2 * ljj + 1, KMAX - 1);
                plb0 = labels[(size_t)(base + kk0) * RR + lr];
                plb1 = labels[(size_t)(base + kk1) * RR + lr];
            }

            u64 c[NB];

            // ---- layer 1: A (x,72) -> B (h), relu ----
#pragma unroll
            for (int jj = 0; jj < NPAIR; jj++) { c[jj*2] = bb1_0; c[jj*2+1] = bb1_1; }
            mlpP<W1_IP>(W1, xbA, lane, c);
#pragma unroll
            for (int jj = 0; jj < NPAIR; jj++) {
                xsB[jj][lane]      = relu2(c[jj*2]);
                xsB[jj][lane + 32] = relu2(c[jj*2+1]);
            }
            __syncwarp();   // sync 2: h RAW (also orders A reads before L2's A writes)

            // ---- layer 2: B (h) -> A (o), relu; o also kept in regs ----
#pragma unroll
            for (int jj = 0; jj < NPAIR; jj++) { c[jj*2] = bb2_0; c[jj*2+1] = bb2_1; }
            mlpP<M_IP>(W2, xbB, lane, c);
            u64 o[NB];
#pragma unroll
            for (int jj = 0; jj < NPAIR; jj++) {
                o[jj*2]   = relu2(c[jj*2]);
                o[jj*2+1] = relu2(c[jj*2+1]);
                xsA[jj][lane]      = o[jj*2];
                xsA[jj][lane + 32] = o[jj*2+1];
            }
            __syncwarp();   // sync 3: o RAW

            // ---- attention layer 1: A (o) -> B, + uc (precomputed), relu ----
#pragma unroll
            for (int jj = 0; jj < NPAIR; jj++) { c[jj*2] = ucd0; c[jj*2+1] = ucd1; }
            mlpP<M_IP>(A1O, xbA, lane, c);
#pragma unroll
            for (int jj = 0; jj < NPAIR; jj++) {
                xsB[jj][lane]      = relu2(c[jj*2]);
                xsB[jj][lane + 32] = relu2(c[jj*2+1]);
            }
            __syncwarp();   // sync 4: a1 RAW (also orders A reads before next staging)

            // ---- attention layer 2: B -> regs, relu ----
#pragma unroll
            for (int jj = 0; jj < NPAIR; jj++) { c[jj*2] = bba2_0; c[jj*2+1] = bba2_1; }
            mlpP<M_IP>(A2, xbB, lane, c);

            // ---- scores (packed pair warp-reduce) + online softmax ----
#pragma unroll
            for (int jj = 0; jj < NPAIR; jj++) {
                u64 part = fmul2(relu2(c[jj*2]),   a3d0);
                part = ffma2(relu2(c[jj*2+1]), a3d1, part);
                part = wsum2(part);
                float s0, s1; upk(part, s0, s1);
                s0 += a3bias; s1 += a3bias;

                float o0lo, o0hi, o1lo, o1hi;
                upk(o[jj*2],   o0lo, o1lo);   // {o_j0[l],    o_j1[l]}
                upk(o[jj*2+1], o0hi, o1hi);   // {o_j0[l+32], o_j1[l+32]}
                if (nv > 2*jj)     smax_upd(s0, pk(o0lo, o0hi), mrun, lrun, agg);
                if (nv > 2*jj + 1) smax_upd(s1, pk(o1lo, o1hi), mrun, lrun, agg);
            }
            // next staging writes A: ordered after this batch's A reads by sync 4
        }

        float inv = 1.0f / lrun;
        float glo, ghi; upk(agg, glo, ghi);
        out[(size_t)b * DD + lane]      = glo * inv;
        out[(size_t)b * DD + lane + 32] = ghi * inv;
    }
}

extern "C" void kernel_launch(void* const* d_in, const int* in_sizes, int n_in,
                              void* d_out, int out_size)
{
    (void)in_sizes; (void)n_in; (void)out_size;
    cudaFuncSetAttribute(sagg_kernel, cudaFuncAttributeMaxDynamicSharedMemorySize, SMEM_TOTAL);

    const int*   nodes  = (const int*)  d_in[0];
    const int*   nidx   = (const int*)  d_in[1];
    const int*   nlen   = (const int*)  d_in[2];
    const float* labels = (const float*)d_in[3];
    const float* u2e    = (const float*)d_in[4];
    const float* w1W    = (const float*)d_in[5];
    const float* w1b    = (const float*)d_in[6];
    const float* w2W    = (const float*)d_in[7];
    const float* w2b    = (const float*)d_in[8];
    const float* a1W    = (const float*)d_in[9];
    const float* a1b    = (const float*)d_in[10];
    const float* a2W    = (const float*)d_in[11];
    const float* a2b    = (const float*)d_in[12];
    const float* a3W    = (const float*)d_in[13];
    const float* a3b    = (const float*)d_in[14];

    reset_ctr<<<1, 1>>>();
    sagg_kernel<<<GRID, NTHREADS, SMEM_TOTAL>>>(
        nodes, nidx, nlen, labels, u2e,
        w1W, w1b, w2W, w2b, a1W, a1b, a2W, a2b, a3W, a3b,
        (float*)d_out);
}